// round 14
// baseline (speedup 1.0000x reference)
#include <cuda_runtime.h>
#include <cuda_fp16.h>
#include <cstdint>

// Attention_63324997812765 — R13: fp16 mma.sync GEMMs, KC=64 chunks
// (half the barriers/chunk overhead of KC=32), NSTAGE=3, 2 CTAs/SM,
// single-read register softmax.

#define B_ 4
#define T_ 2048
#define E_ 1024
#define TM 128
#define TN 128
#define KC 64
#define NTH 256     // 8 warps: 4x2 -> warp tile 32x64
#define ROWB 144    // 128B data + 16B pad (conflict-free ldmatrix)
#define A_OFF 0
#define B_OFF (128 * ROWB)         // 18432
#define STAGEB (2 * 128 * ROWB)    // 36864
#define NSTAGE 3
#define DSMEM (NSTAGE * STAGEB)    // 110592 -> 2 CTAs/SM (221KB of 228KB)

// ---------------------------------------------------------------------------
__device__ __forceinline__ uint32_t smem_u32(const void* p) {
    uint32_t a;
    asm("{ .reg .u64 t; cvta.to.shared.u64 t, %1; cvt.u32.u64 %0, t; }" : "=r"(a) : "l"(p));
    return a;
}
__device__ __forceinline__ void cpasync16(uint32_t s, const void* g) {
    asm volatile("cp.async.cg.shared.global [%0], [%1], 16;" :: "r"(s), "l"(g));
}
__device__ __forceinline__ void cp_commit() { asm volatile("cp.async.commit_group;" ::: "memory"); }
template <int N> __device__ __forceinline__ void cp_wait() {
    asm volatile("cp.async.wait_group %0;" :: "n"(N) : "memory");
}
__device__ __forceinline__ void ldsm4(uint32_t* r, uint32_t addr) {
    asm volatile("ldmatrix.sync.aligned.m8n8.x4.shared.b16 {%0,%1,%2,%3}, [%4];"
                 : "=r"(r[0]), "=r"(r[1]), "=r"(r[2]), "=r"(r[3]) : "r"(addr));
}
__device__ __forceinline__ void mma16816(float* c, const uint32_t* a, const uint32_t* b) {
    asm volatile(
        "mma.sync.aligned.m16n8k16.row.col.f32.f16.f16.f32 "
        "{%0,%1,%2,%3}, {%4,%5,%6,%7}, {%8,%9}, {%0,%1,%2,%3};"
        : "+f"(c[0]), "+f"(c[1]), "+f"(c[2]), "+f"(c[3])
        : "r"(a[0]), "r"(a[1]), "r"(a[2]), "r"(a[3]), "r"(b[0]), "r"(b[1]));
}

// ---------------------------------------------------------------------------
__device__ __half g_qh[B_ * T_ * E_], g_kh[B_ * T_ * E_], g_vh[B_ * T_ * E_];
__device__ __half g_wqh[E_ * E_], g_wkh[E_ * E_], g_wvh[E_ * E_];
__device__ __half g_QP[B_ * T_ * E_], g_KP[B_ * T_ * E_];
__device__ __half g_VPt[B_ * E_ * T_];           // transposed [b][e][t]
__device__ __half g_P[B_ * T_ * T_];
__device__ float g_S[B_ * T_ * T_];

struct alignas(16) half8 { __half v[8]; };

// ---------------------------------------------------------------------------
__global__ void __launch_bounds__(256) convert3_kernel(
    const float* __restrict__ x0, const float* __restrict__ x1, const float* __restrict__ x2,
    __half* __restrict__ y0, __half* __restrict__ y1, __half* __restrict__ y2, int n8)
{
    const int z = blockIdx.z;
    const float* x = (z == 0) ? x0 : (z == 1) ? x1 : x2;
    __half* y = (z == 0) ? y0 : (z == 1) ? y1 : y2;
    int i = blockIdx.x * 256 + threadIdx.x;
    if (i >= n8) return;
    float4 f0 = ((const float4*)x)[i * 2];
    float4 f1 = ((const float4*)x)[i * 2 + 1];
    half8 h;
    h.v[0] = __float2half(f0.x); h.v[1] = __float2half(f0.y);
    h.v[2] = __float2half(f0.z); h.v[3] = __float2half(f0.w);
    h.v[4] = __float2half(f1.x); h.v[5] = __float2half(f1.y);
    h.v[6] = __float2half(f1.z); h.v[7] = __float2half(f1.w);
    ((half8*)y)[i] = h;
}

// ---------------------------------------------------------------------------
// NT GEMM, fp16 single-pass, mma.sync. 128x128 CTA, 8 warps (4x2), 32x64.
// ---------------------------------------------------------------------------
template <int MODE>
__global__ void __launch_bounds__(NTH, 2)
gemm_fp16(const __half* __restrict__ A, const __half* __restrict__ Bm,
          int lda, int ldb, int Kdim,
          const float* __restrict__ bias,
          float* __restrict__ Of, __half* __restrict__ Oh,
          const int* __restrict__ causalp)
{
    const int bm = blockIdx.y, bn = blockIdx.x, bz = blockIdx.z;
    int causal = 0;
    if (MODE >= 2) causal = *causalp;
    if (MODE == 2 && causal && bn > bm) return;

    int Klen = Kdim;
    if (MODE == 3 && causal) Klen = (bm + 1) * TM;

    size_t aOff = 0, bOff = 0;
    if (MODE == 2) { aOff = (size_t)bz * T_ * E_; bOff = (size_t)bz * T_ * E_; }
    if (MODE == 3) { aOff = (size_t)bz * T_ * T_; bOff = (size_t)bz * E_ * T_; }
    const __half* pA = A + aOff;
    const __half* pB = Bm + bOff;

    extern __shared__ char dsm[];
    const uint32_t sbase = smem_u32(dsm);

    const int t = threadIdx.x;
    const int wid = t >> 5, lane = t & 31;
    const int wm = wid >> 1, wn = wid & 1;      // 4x2 warps, 32x64 tiles
    const int mrow0 = bm * TM, nrow0 = bn * TN;

    // cp.async: 2 threads/row, each does 4 of 8 16B segs per matrix.
    const int crow = t >> 1;
    const int cseg = (t & 1) * 4;
    const uint32_t cso = (uint32_t)(crow * ROWB + cseg * 16);

    const uint32_t aoff = (uint32_t)((lane & 15) * ROWB + (lane >> 4) * 16);
    const uint32_t boff = (uint32_t)((((lane & 7) + ((lane >> 1) & 8)) * ROWB) + (lane & 8) * 2);

    float acc[2][8][4] = {};

    const int nchunk = Klen / KC;

    auto prefetch = [&](int ch) {
        const int k0 = ch * KC;
        const uint32_t ss = sbase + (uint32_t)(ch % NSTAGE) * STAGEB;
        const size_t ga = (size_t)(mrow0 + crow) * lda + k0 + cseg * 8;
        const size_t gb = (size_t)(nrow0 + crow) * ldb + k0 + cseg * 8;
#pragma unroll
        for (int s2 = 0; s2 < 4; s2++) {
            cpasync16(ss + A_OFF + cso + s2 * 16, pA + ga + s2 * 8);
            cpasync16(ss + B_OFF + cso + s2 * 16, pB + gb + s2 * 8);
        }
        cp_commit();
    };

    prefetch(0);
    if (nchunk > 1) prefetch(1);

    for (int ch = 0; ch < nchunk; ch++) {
        if (ch + 1 < nchunk) cp_wait<1>(); else cp_wait<0>();
        __syncthreads();
        if (ch + 2 < nchunk) prefetch(ch + 2);

        const uint32_t ss = sbase + (uint32_t)(ch % NSTAGE) * STAGEB;

#pragma unroll
        for (int k16 = 0; k16 < 4; k16++) {
            const uint32_t kb = (uint32_t)(k16 * 32);
            uint32_t ah[2][4], bh[4][4];
#pragma unroll
            for (int mt = 0; mt < 2; mt++)
                ldsm4(ah[mt], ss + A_OFF + (uint32_t)((wm * 32 + mt * 16) * ROWB) + kb + aoff);
#pragma unroll
            for (int n2 = 0; n2 < 4; n2++)
                ldsm4(bh[n2], ss + B_OFF + (uint32_t)((wn * 64 + n2 * 16) * ROWB) + kb + boff);

#pragma unroll
            for (int n2 = 0; n2 < 4; n2++)
#pragma unroll
                for (int mt = 0; mt < 2; mt++)
#pragma unroll
                    for (int h2 = 0; h2 < 2; h2++)
                        mma16816(acc[mt][n2 * 2 + h2], ah[mt], &bh[n2][h2 * 2]);
        }
    }

    // ---------------- Epilogue ----------------
#pragma unroll
    for (int mt = 0; mt < 2; mt++) {
#pragma unroll
        for (int nt = 0; nt < 8; nt++) {
            const float* c = acc[mt][nt];
            const int row = bm * TM + wm * 32 + mt * 16 + (lane >> 2);
            const int col = bn * TN + wn * 64 + nt * 8 + (lane & 3) * 2;

            if constexpr (MODE == 0) {
                const float b0 = bias[col], b1 = bias[col + 1];
#pragma unroll
                for (int h = 0; h < 2; h++) {
                    const int r2 = row + h * 8;
                    __half2 hv = __floats2half2_rn(c[h * 2 + 0] + b0, c[h * 2 + 1] + b1);
                    *(__half2*)(Oh + (size_t)r2 * E_ + col) = hv;
                }
            } else if constexpr (MODE == 1) {
                const float b0 = bias[col], b1 = bias[col + 1];
#pragma unroll
                for (int h = 0; h < 2; h++) {
                    const int r2 = row + h * 8;
                    const int bb = r2 >> 11, tok = r2 & (T_ - 1);
                    const size_t i0 = ((size_t)bb * E_ + col) * T_ + tok;
                    Oh[i0]      = __float2half(c[h * 2 + 0] + b0);
                    Oh[i0 + T_] = __float2half(c[h * 2 + 1] + b1);
                }
            } else if constexpr (MODE == 2) {
                const float sc = 0.03125f;
#pragma unroll
                for (int h = 0; h < 2; h++) {
                    const int r2 = row + h * 8;
                    float2 f = make_float2(c[h * 2 + 0] * sc, c[h * 2 + 1] * sc);
                    *(float2*)(Of + (size_t)bz * T_ * T_ + (size_t)r2 * T_ + col) = f;
                }
            } else {
#pragma unroll
                for (int h = 0; h < 2; h++) {
                    const int r2 = row + h * 8;
                    float2 f = make_float2(c[h * 2 + 0], c[h * 2 + 1]);
                    *(float2*)(Of + (size_t)bz * T_ * E_ + (size_t)r2 * E_ + col) = f;
                }
            }
        }
    }
}

// ---------------------------------------------------------------------------
// Row softmax, single global read: row cached in 8 regs/thread.
// ---------------------------------------------------------------------------
__global__ void __launch_bounds__(256) softmax_kernel(const float* __restrict__ S,
                                                      __half* __restrict__ P,
                                                      const int* __restrict__ causalp)
{
    const int b = blockIdx.y, i = blockIdx.x;
    const float* row = S + ((size_t)b * T_ + i) * T_;
    __half* ph = P + ((size_t)b * T_ + i) * T_;
    const int causal = *causalp;
    const int jmax = causal ? i : (T_ - 1);
    const int t = threadIdx.x;

    __shared__ float red[256];

    float vals[8];
    float lm = -3.4e38f;
#pragma unroll
    for (int it = 0; it < 8; it++) {
        const int j = t + it * 256;
        vals[it] = (j <= jmax) ? row[j] : -3.4e38f;
        lm = fmaxf(lm, vals[it]);
    }
    red[t] = lm; __syncthreads();
    for (int s = 128; s > 0; s >>= 1) {
        if (t < s) red[t] = fmaxf(red[t], red[t + s]);
        __syncthreads();
    }
    const float m = red[0];
    __syncthreads();

    float ls = 0.f;
#pragma unroll
    for (int it = 0; it < 8; it++) {
        const int j = t + it * 256;
        if (j <= jmax) {
            const float e = __expf(vals[it] - m);
            vals[it] = e;
            ls += e;
        }
    }
    red[t] = ls; __syncthreads();
    for (int s = 128; s > 0; s >>= 1) {
        if (t < s) red[t] += red[t + s];
        __syncthreads();
    }
    const float inv = 1.f / red[0];

#pragma unroll
    for (int it = 0; it < 8; it++) {
        const int j = t + it * 256;
        if (j <= jmax) ph[j] = __float2half(vals[it] * inv);
    }
    if (causal) {
        const int zend = ((i >> 7) + 1) << 7;
        for (int j = i + 1 + t; j < zend; j += 256) ph[j] = __float2half(0.f);
    }
}

// ---------------------------------------------------------------------------
extern "C" void kernel_launch(void* const* d_in, const int* in_sizes, int n_in,
                              void* d_out, int out_size)
{
    const float* q    = (const float*)d_in[0];
    const float* k    = (const float*)d_in[1];
    const float* v    = (const float*)d_in[2];
    const float* wq_w = (const float*)d_in[3];
    const float* wq_b = (const float*)d_in[4];
    const float* wk_w = (const float*)d_in[5];
    const float* wk_b = (const float*)d_in[6];
    const float* wv_w = (const float*)d_in[7];
    const float* wv_b = (const float*)d_in[8];
    const int* causal = (const int*)d_in[9];
    float* out = (float*)d_out;

    void *qh, *kh, *vh, *wqh, *wkh, *wvh, *QP, *KP, *VPt, *P, *Sp;
    cudaGetSymbolAddress(&qh, g_qh);   cudaGetSymbolAddress(&kh, g_kh);
    cudaGetSymbolAddress(&vh, g_vh);
    cudaGetSymbolAddress(&wqh, g_wqh); cudaGetSymbolAddress(&wkh, g_wkh);
    cudaGetSymbolAddress(&wvh, g_wvh);
    cudaGetSymbolAddress(&QP, g_QP);   cudaGetSymbolAddress(&KP, g_KP);
    cudaGetSymbolAddress(&VPt, g_VPt); cudaGetSymbolAddress(&P, g_P);
    cudaGetSymbolAddress(&Sp, g_S);

    cudaFuncSetAttribute(gemm_fp16<0>, cudaFuncAttributeMaxDynamicSharedMemorySize, DSMEM);
    cudaFuncSetAttribute(gemm_fp16<1>, cudaFuncAttributeMaxDynamicSharedMemorySize, DSMEM);
    cudaFuncSetAttribute(gemm_fp16<2>, cudaFuncAttributeMaxDynamicSharedMemorySize, DSMEM);
    cudaFuncSetAttribute(gemm_fp16<3>, cudaFuncAttributeMaxDynamicSharedMemorySize, DSMEM);

    // 1) fp32 -> fp16 converts
    const int nQKV8 = B_ * T_ * E_ / 8, nW8 = E_ * E_ / 8;
    dim3 gz1(nQKV8 / 256, 1, 3), gz2(nW8 / 256, 1, 3);
    convert3_kernel<<<gz1, 256>>>(q, k, v, (__half*)qh, (__half*)kh, (__half*)vh, nQKV8);
    convert3_kernel<<<gz2, 256>>>(wq_w, wk_w, wv_w,
                                  (__half*)wqh, (__half*)wkh, (__half*)wvh, nW8);

    // 2) Projections
    dim3 gp(E_ / TN, (B_ * T_) / TM, 1);   // 8 x 64
    gemm_fp16<0><<<gp, NTH, DSMEM>>>((__half*)qh, (__half*)wqh, E_, E_, E_,
                                     wq_b, nullptr, (__half*)QP, nullptr);
    gemm_fp16<0><<<gp, NTH, DSMEM>>>((__half*)kh, (__half*)wkh, E_, E_, E_,
                                     wk_b, nullptr, (__half*)KP, nullptr);
    gemm_fp16<1><<<gp, NTH, DSMEM>>>((__half*)vh, (__half*)wvh, E_, E_, E_,
                                     wv_b, nullptr, (__half*)VPt, nullptr);

    // 3) Scores (lower-triangular tiles only)
    dim3 gs(T_ / TN, T_ / TM, B_);         // 16 x 16 x 4
    gemm_fp16<2><<<gs, NTH, DSMEM>>>((__half*)QP, (__half*)KP, E_, E_, E_,
                                     nullptr, (float*)Sp, nullptr, causal);

    // 4) Softmax -> fp16 P
    dim3 gm(T_, B_);
    softmax_kernel<<<gm, 256>>>((const float*)Sp, (__half*)P, causal);

    // 5) O = P @ VPt^T (causal K truncation)
    dim3 gv(E_ / TN, T_ / TM, B_);         // 8 x 16 x 4
    gemm_fp16<3><<<gv, NTH, DSMEM>>>((__half*)P, (__half*)VPt, T_, T_, T_,
                                     nullptr, out, nullptr, causal);
}

// round 15
// speedup vs baseline: 1.1751x; 1.1751x over previous
#include <cuda_runtime.h>
#include <cuda_fp16.h>
#include <cstdint>

// Attention_63324997812765 — R14: R10 GEMM core (proven best: KC=32, 4-stage,
// 3-deep lookahead) + single merged projection launch (grid.z) + heavy-first
// CTA ordering for causal kernels + register softmax.

#define B_ 4
#define T_ 2048
#define E_ 1024
#define TM 128
#define TN 128
#define KC 32
#define NTH 256     // 8 warps: 4x2 -> warp tile 32x64
#define ROWB 80     // 64B data + 16B pad (conflict-free ldmatrix)
#define A_OFF 0
#define B_OFF (128 * ROWB)         // 10240
#define STAGEB (2 * 128 * ROWB)    // 20480
#define NSTAGE 4
#define DSMEM (NSTAGE * STAGEB)    // 81920 -> 2 CTAs/SM

// ---------------------------------------------------------------------------
__device__ __forceinline__ uint32_t smem_u32(const void* p) {
    uint32_t a;
    asm("{ .reg .u64 t; cvta.to.shared.u64 t, %1; cvt.u32.u64 %0, t; }" : "=r"(a) : "l"(p));
    return a;
}
__device__ __forceinline__ void cpasync16(uint32_t s, const void* g) {
    asm volatile("cp.async.cg.shared.global [%0], [%1], 16;" :: "r"(s), "l"(g));
}
__device__ __forceinline__ void cp_commit() { asm volatile("cp.async.commit_group;" ::: "memory"); }
template <int N> __device__ __forceinline__ void cp_wait() {
    asm volatile("cp.async.wait_group %0;" :: "n"(N) : "memory");
}
__device__ __forceinline__ void ldsm4(uint32_t* r, uint32_t addr) {
    asm volatile("ldmatrix.sync.aligned.m8n8.x4.shared.b16 {%0,%1,%2,%3}, [%4];"
                 : "=r"(r[0]), "=r"(r[1]), "=r"(r[2]), "=r"(r[3]) : "r"(addr));
}
__device__ __forceinline__ void mma16816(float* c, const uint32_t* a, const uint32_t* b) {
    asm volatile(
        "mma.sync.aligned.m16n8k16.row.col.f32.f16.f16.f32 "
        "{%0,%1,%2,%3}, {%4,%5,%6,%7}, {%8,%9}, {%0,%1,%2,%3};"
        : "+f"(c[0]), "+f"(c[1]), "+f"(c[2]), "+f"(c[3])
        : "r"(a[0]), "r"(a[1]), "r"(a[2]), "r"(a[3]), "r"(b[0]), "r"(b[1]));
}

// ---------------------------------------------------------------------------
__device__ __half g_qh[B_ * T_ * E_], g_kh[B_ * T_ * E_], g_vh[B_ * T_ * E_];
__device__ __half g_wqh[E_ * E_], g_wkh[E_ * E_], g_wvh[E_ * E_];
__device__ __half g_QP[B_ * T_ * E_], g_KP[B_ * T_ * E_];
__device__ __half g_VPt[B_ * E_ * T_];           // transposed [b][e][t]
__device__ __half g_P[B_ * T_ * T_];
__device__ float g_S[B_ * T_ * T_];

struct alignas(16) half8 { __half v[8]; };

// ---------------------------------------------------------------------------
__global__ void __launch_bounds__(256) convert3_kernel(
    const float* __restrict__ x0, const float* __restrict__ x1, const float* __restrict__ x2,
    __half* __restrict__ y0, __half* __restrict__ y1, __half* __restrict__ y2, int n8)
{
    const int z = blockIdx.z;
    const float* x = (z == 0) ? x0 : (z == 1) ? x1 : x2;
    __half* y = (z == 0) ? y0 : (z == 1) ? y1 : y2;
    int i = blockIdx.x * 256 + threadIdx.x;
    if (i >= n8) return;
    float4 f0 = ((const float4*)x)[i * 2];
    float4 f1 = ((const float4*)x)[i * 2 + 1];
    half8 h;
    h.v[0] = __float2half(f0.x); h.v[1] = __float2half(f0.y);
    h.v[2] = __float2half(f0.z); h.v[3] = __float2half(f0.w);
    h.v[4] = __float2half(f1.x); h.v[5] = __float2half(f1.y);
    h.v[6] = __float2half(f1.z); h.v[7] = __float2half(f1.w);
    ((half8*)y)[i] = h;
}

// ---------------------------------------------------------------------------
// Merged projections: grid.z = 0(Q) / 1(K) / 2(V, transposed output).
// NT GEMM 128x128 CTA, 8 warps (4x2), warp tile 32x64, R10 pipeline.
// ---------------------------------------------------------------------------
__global__ void __launch_bounds__(NTH, 2)
proj_fp16(const __half* __restrict__ xq, const __half* __restrict__ xk,
          const __half* __restrict__ xv,
          const __half* __restrict__ wq, const __half* __restrict__ wk,
          const __half* __restrict__ wv,
          const float* __restrict__ bq, const float* __restrict__ bk,
          const float* __restrict__ bv,
          __half* __restrict__ QP, __half* __restrict__ KP, __half* __restrict__ VPt)
{
    const int z = blockIdx.z;
    const __half* pA = (z == 0) ? xq : (z == 1) ? xk : xv;
    const __half* pB = (z == 0) ? wq : (z == 1) ? wk : wv;
    const float* bias = (z == 0) ? bq : (z == 1) ? bk : bv;

    const int bm = blockIdx.y, bn = blockIdx.x;

    extern __shared__ char dsm[];
    const uint32_t sbase = smem_u32(dsm);

    const int t = threadIdx.x;
    const int wid = t >> 5, lane = t & 31;
    const int wm = wid >> 1, wn = wid & 1;
    const int mrow0 = bm * TM, nrow0 = bn * TN;

    const int crow = t >> 1;
    const int cseg = (t & 1) * 2;
    const uint32_t cso = (uint32_t)(crow * ROWB + cseg * 16);

    const uint32_t aoff = (uint32_t)((lane & 15) * ROWB + (lane >> 4) * 16);
    const uint32_t boff = (uint32_t)((((lane & 7) + ((lane >> 1) & 8)) * ROWB) + (lane & 8) * 2);

    float acc[2][8][4] = {};

    const int nchunk = E_ / KC;

    auto prefetch = [&](int ch) {
        const int k0 = ch * KC;
        const uint32_t ss = sbase + (uint32_t)(ch & (NSTAGE - 1)) * STAGEB;
        const size_t ga = (size_t)(mrow0 + crow) * E_ + k0 + cseg * 8;
        const size_t gb = (size_t)(nrow0 + crow) * E_ + k0 + cseg * 8;
        cpasync16(ss + A_OFF + cso,      pA + ga);
        cpasync16(ss + A_OFF + cso + 16, pA + ga + 8);
        cpasync16(ss + B_OFF + cso,      pB + gb);
        cpasync16(ss + B_OFF + cso + 16, pB + gb + 8);
        cp_commit();
    };

    prefetch(0); prefetch(1); prefetch(2);

    for (int ch = 0; ch < nchunk; ch++) {
        if (ch + 2 < nchunk)      cp_wait<2>();
        else if (ch + 1 < nchunk) cp_wait<1>();
        else                      cp_wait<0>();
        __syncthreads();
        if (ch + 3 < nchunk) prefetch(ch + 3);

        const uint32_t ss = sbase + (uint32_t)(ch & (NSTAGE - 1)) * STAGEB;

#pragma unroll
        for (int k16 = 0; k16 < 2; k16++) {
            const uint32_t kb = (uint32_t)(k16 * 32);
            uint32_t ah[2][4], bh[4][4];
#pragma unroll
            for (int mt = 0; mt < 2; mt++)
                ldsm4(ah[mt], ss + A_OFF + (uint32_t)((wm * 32 + mt * 16) * ROWB) + kb + aoff);
#pragma unroll
            for (int n2 = 0; n2 < 4; n2++)
                ldsm4(bh[n2], ss + B_OFF + (uint32_t)((wn * 64 + n2 * 16) * ROWB) + kb + boff);

#pragma unroll
            for (int n2 = 0; n2 < 4; n2++)
#pragma unroll
                for (int mt = 0; mt < 2; mt++)
#pragma unroll
                    for (int h2 = 0; h2 < 2; h2++)
                        mma16816(acc[mt][n2 * 2 + h2], ah[mt], &bh[n2][h2 * 2]);
        }
    }

    __half* Oh = (z == 0) ? QP : (z == 1) ? KP : VPt;

#pragma unroll
    for (int mt = 0; mt < 2; mt++) {
#pragma unroll
        for (int nt = 0; nt < 8; nt++) {
            const float* c = acc[mt][nt];
            const int row = bm * TM + wm * 32 + mt * 16 + (lane >> 2);
            const int col = bn * TN + wn * 64 + nt * 8 + (lane & 3) * 2;
            const float b0 = bias[col], b1 = bias[col + 1];
            if (z < 2) {
#pragma unroll
                for (int h = 0; h < 2; h++) {
                    const int r2 = row + h * 8;
                    __half2 hv = __floats2half2_rn(c[h * 2 + 0] + b0, c[h * 2 + 1] + b1);
                    *(__half2*)(Oh + (size_t)r2 * E_ + col) = hv;
                }
            } else {
#pragma unroll
                for (int h = 0; h < 2; h++) {
                    const int r2 = row + h * 8;
                    const int bb = r2 >> 11, tok = r2 & (T_ - 1);
                    const size_t i0 = ((size_t)bb * E_ + col) * T_ + tok;
                    Oh[i0]      = __float2half(c[h * 2 + 0] + b0);
                    Oh[i0 + T_] = __float2half(c[h * 2 + 1] + b1);
                }
            }
        }
    }
}

// ---------------------------------------------------------------------------
// MODE 2: scores (*1/32 -> fp32 S, causal tile skip)  MODE 3: PV (K truncated)
// bm reversed so heavy tiles schedule first.
// ---------------------------------------------------------------------------
template <int MODE>
__global__ void __launch_bounds__(NTH, 2)
gemm_fp16(const __half* __restrict__ A, const __half* __restrict__ Bm,
          int lda, int ldb, int Kdim,
          float* __restrict__ Of, const int* __restrict__ causalp)
{
    const int bm = (int)gridDim.y - 1 - (int)blockIdx.y;   // heavy-first
    const int bn = blockIdx.x, bz = blockIdx.z;
    const int causal = *causalp;
    if (MODE == 2 && causal && bn > bm) return;

    int Klen = Kdim;
    if (MODE == 3 && causal) Klen = (bm + 1) * TM;

    size_t aOff, bOff;
    if (MODE == 2) { aOff = (size_t)bz * T_ * E_; bOff = (size_t)bz * T_ * E_; }
    else           { aOff = (size_t)bz * T_ * T_; bOff = (size_t)bz * E_ * T_; }
    const __half* pA = A + aOff;
    const __half* pB = Bm + bOff;

    extern __shared__ char dsm[];
    const uint32_t sbase = smem_u32(dsm);

    const int t = threadIdx.x;
    const int wid = t >> 5, lane = t & 31;
    const int wm = wid >> 1, wn = wid & 1;
    const int mrow0 = bm * TM, nrow0 = bn * TN;

    const int crow = t >> 1;
    const int cseg = (t & 1) * 2;
    const uint32_t cso = (uint32_t)(crow * ROWB + cseg * 16);

    const uint32_t aoff = (uint32_t)((lane & 15) * ROWB + (lane >> 4) * 16);
    const uint32_t boff = (uint32_t)((((lane & 7) + ((lane >> 1) & 8)) * ROWB) + (lane & 8) * 2);

    float acc[2][8][4] = {};

    const int nchunk = Klen / KC;

    auto prefetch = [&](int ch) {
        const int k0 = ch * KC;
        const uint32_t ss = sbase + (uint32_t)(ch & (NSTAGE - 1)) * STAGEB;
        const size_t ga = (size_t)(mrow0 + crow) * lda + k0 + cseg * 8;
        const size_t gb = (size_t)(nrow0 + crow) * ldb + k0 + cseg * 8;
        cpasync16(ss + A_OFF + cso,      pA + ga);
        cpasync16(ss + A_OFF + cso + 16, pA + ga + 8);
        cpasync16(ss + B_OFF + cso,      pB + gb);
        cpasync16(ss + B_OFF + cso + 16, pB + gb + 8);
        cp_commit();
    };

    prefetch(0);
    if (nchunk > 1) prefetch(1);
    if (nchunk > 2) prefetch(2);

    for (int ch = 0; ch < nchunk; ch++) {
        if (ch + 2 < nchunk)      cp_wait<2>();
        else if (ch + 1 < nchunk) cp_wait<1>();
        else                      cp_wait<0>();
        __syncthreads();
        if (ch + 3 < nchunk) prefetch(ch + 3);

        const uint32_t ss = sbase + (uint32_t)(ch & (NSTAGE - 1)) * STAGEB;

#pragma unroll
        for (int k16 = 0; k16 < 2; k16++) {
            const uint32_t kb = (uint32_t)(k16 * 32);
            uint32_t ah[2][4], bh[4][4];
#pragma unroll
            for (int mt = 0; mt < 2; mt++)
                ldsm4(ah[mt], ss + A_OFF + (uint32_t)((wm * 32 + mt * 16) * ROWB) + kb + aoff);
#pragma unroll
            for (int n2 = 0; n2 < 4; n2++)
                ldsm4(bh[n2], ss + B_OFF + (uint32_t)((wn * 64 + n2 * 16) * ROWB) + kb + boff);

#pragma unroll
            for (int n2 = 0; n2 < 4; n2++)
#pragma unroll
                for (int mt = 0; mt < 2; mt++)
#pragma unroll
                    for (int h2 = 0; h2 < 2; h2++)
                        mma16816(acc[mt][n2 * 2 + h2], ah[mt], &bh[n2][h2 * 2]);
        }
    }

#pragma unroll
    for (int mt = 0; mt < 2; mt++) {
#pragma unroll
        for (int nt = 0; nt < 8; nt++) {
            const float* c = acc[mt][nt];
            const int row = bm * TM + wm * 32 + mt * 16 + (lane >> 2);
            const int col = bn * TN + wn * 64 + nt * 8 + (lane & 3) * 2;
            if constexpr (MODE == 2) {
                const float sc = 0.03125f;
#pragma unroll
                for (int h = 0; h < 2; h++) {
                    const int r2 = row + h * 8;
                    float2 f = make_float2(c[h * 2 + 0] * sc, c[h * 2 + 1] * sc);
                    *(float2*)(Of + (size_t)bz * T_ * T_ + (size_t)r2 * T_ + col) = f;
                }
            } else {
#pragma unroll
                for (int h = 0; h < 2; h++) {
                    const int r2 = row + h * 8;
                    float2 f = make_float2(c[h * 2 + 0], c[h * 2 + 1]);
                    *(float2*)(Of + (size_t)bz * T_ * E_ + (size_t)r2 * E_ + col) = f;
                }
            }
        }
    }
}

// ---------------------------------------------------------------------------
// Row softmax, single global read: row cached in 8 regs/thread.
// ---------------------------------------------------------------------------
__global__ void __launch_bounds__(256) softmax_kernel(const float* __restrict__ S,
                                                      __half* __restrict__ P,
                                                      const int* __restrict__ causalp)
{
    const int b = blockIdx.y, i = blockIdx.x;
    const float* row = S + ((size_t)b * T_ + i) * T_;
    __half* ph = P + ((size_t)b * T_ + i) * T_;
    const int causal = *causalp;
    const int jmax = causal ? i : (T_ - 1);
    const int t = threadIdx.x;

    __shared__ float red[256];

    float vals[8];
    float lm = -3.4e38f;
#pragma unroll
    for (int it = 0; it < 8; it++) {
        const int j = t + it * 256;
        vals[it] = (j <= jmax) ? row[j] : -3.4e38f;
        lm = fmaxf(lm, vals[it]);
    }
    red[t] = lm; __syncthreads();
    for (int s = 128; s > 0; s >>= 1) {
        if (t < s) red[t] = fmaxf(red[t], red[t + s]);
        __syncthreads();
    }
    const float m = red[0];
    __syncthreads();

    float ls = 0.f;
#pragma unroll
    for (int it = 0; it < 8; it++) {
        const int j = t + it * 256;
        if (j <= jmax) {
            const float e = __expf(vals[it] - m);
            vals[it] = e;
            ls += e;
        }
    }
    red[t] = ls; __syncthreads();
    for (int s = 128; s > 0; s >>= 1) {
        if (t < s) red[t] += red[t + s];
        __syncthreads();
    }
    const float inv = 1.f / red[0];

#pragma unroll
    for (int it = 0; it < 8; it++) {
        const int j = t + it * 256;
        if (j <= jmax) ph[j] = __float2half(vals[it] * inv);
    }
    if (causal) {
        const int zend = ((i >> 7) + 1) << 7;
        for (int j = i + 1 + t; j < zend; j += 256) ph[j] = __float2half(0.f);
    }
}

// ---------------------------------------------------------------------------
extern "C" void kernel_launch(void* const* d_in, const int* in_sizes, int n_in,
                              void* d_out, int out_size)
{
    const float* q    = (const float*)d_in[0];
    const float* k    = (const float*)d_in[1];
    const float* v    = (const float*)d_in[2];
    const float* wq_w = (const float*)d_in[3];
    const float* wq_b = (const float*)d_in[4];
    const float* wk_w = (const float*)d_in[5];
    const float* wk_b = (const float*)d_in[6];
    const float* wv_w = (const float*)d_in[7];
    const float* wv_b = (const float*)d_in[8];
    const int* causal = (const int*)d_in[9];
    float* out = (float*)d_out;

    void *qh, *kh, *vh, *wqh, *wkh, *wvh, *QP, *KP, *VPt, *P, *Sp;
    cudaGetSymbolAddress(&qh, g_qh);   cudaGetSymbolAddress(&kh, g_kh);
    cudaGetSymbolAddress(&vh, g_vh);
    cudaGetSymbolAddress(&wqh, g_wqh); cudaGetSymbolAddress(&wkh, g_wkh);
    cudaGetSymbolAddress(&wvh, g_wvh);
    cudaGetSymbolAddress(&QP, g_QP);   cudaGetSymbolAddress(&KP, g_KP);
    cudaGetSymbolAddress(&VPt, g_VPt); cudaGetSymbolAddress(&P, g_P);
    cudaGetSymbolAddress(&Sp, g_S);

    cudaFuncSetAttribute(proj_fp16,    cudaFuncAttributeMaxDynamicSharedMemorySize, DSMEM);
    cudaFuncSetAttribute(gemm_fp16<2>, cudaFuncAttributeMaxDynamicSharedMemorySize, DSMEM);
    cudaFuncSetAttribute(gemm_fp16<3>, cudaFuncAttributeMaxDynamicSharedMemorySize, DSMEM);

    // 1) fp32 -> fp16 converts
    const int nQKV8 = B_ * T_ * E_ / 8, nW8 = E_ * E_ / 8;
    dim3 gz1(nQKV8 / 256, 1, 3), gz2(nW8 / 256, 1, 3);
    convert3_kernel<<<gz1, 256>>>(q, k, v, (__half*)qh, (__half*)kh, (__half*)vh, nQKV8);
    convert3_kernel<<<gz2, 256>>>(wq_w, wk_w, wv_w,
                                  (__half*)wqh, (__half*)wkh, (__half*)wvh, nW8);

    // 2) All three projections in ONE launch (grid.z = Q/K/V)
    dim3 gp(E_ / TN, (B_ * T_) / TM, 3);   // 8 x 64 x 3 = 1536 CTAs
    proj_fp16<<<gp, NTH, DSMEM>>>((__half*)qh, (__half*)kh, (__half*)vh,
                                  (__half*)wqh, (__half*)wkh, (__half*)wvh,
                                  wq_b, wk_b, wv_b,
                                  (__half*)QP, (__half*)KP, (__half*)VPt);

    // 3) Scores (heavy-first, causal skip)
    dim3 gs(T_ / TN, T_ / TM, B_);         // 16 x 16 x 4
    gemm_fp16<2><<<gs, NTH, DSMEM>>>((__half*)QP, (__half*)KP, E_, E_, E_,
                                     (float*)Sp, causal);

    // 4) Softmax -> fp16 P
    dim3 gm(T_, B_);
    softmax_kernel<<<gm, 256>>>((const float*)Sp, (__half*)P, causal);

    // 5) PV (heavy-first, K truncation)
    dim3 gv(E_ / TN, T_ / TM, B_);         // 8 x 16 x 4
    gemm_fp16<3><<<gv, NTH, DSMEM>>>((__half*)P, (__half*)VPt, T_, T_, T_,
                                     out, causal);
}

// round 16
// speedup vs baseline: 1.1761x; 1.0009x over previous
#include <cuda_runtime.h>
#include <cuda_fp16.h>
#include <cstdint>

// Attention_63324997812765 — R14: R10 GEMM core (proven best: KC=32, 4-stage,
// 3-deep lookahead) + single merged projection launch (grid.z) + heavy-first
// CTA ordering for causal kernels + register softmax.

#define B_ 4
#define T_ 2048
#define E_ 1024
#define TM 128
#define TN 128
#define KC 32
#define NTH 256     // 8 warps: 4x2 -> warp tile 32x64
#define ROWB 80     // 64B data + 16B pad (conflict-free ldmatrix)
#define A_OFF 0
#define B_OFF (128 * ROWB)         // 10240
#define STAGEB (2 * 128 * ROWB)    // 20480
#define NSTAGE 4
#define DSMEM (NSTAGE * STAGEB)    // 81920 -> 2 CTAs/SM

// ---------------------------------------------------------------------------
__device__ __forceinline__ uint32_t smem_u32(const void* p) {
    uint32_t a;
    asm("{ .reg .u64 t; cvta.to.shared.u64 t, %1; cvt.u32.u64 %0, t; }" : "=r"(a) : "l"(p));
    return a;
}
__device__ __forceinline__ void cpasync16(uint32_t s, const void* g) {
    asm volatile("cp.async.cg.shared.global [%0], [%1], 16;" :: "r"(s), "l"(g));
}
__device__ __forceinline__ void cp_commit() { asm volatile("cp.async.commit_group;" ::: "memory"); }
template <int N> __device__ __forceinline__ void cp_wait() {
    asm volatile("cp.async.wait_group %0;" :: "n"(N) : "memory");
}
__device__ __forceinline__ void ldsm4(uint32_t* r, uint32_t addr) {
    asm volatile("ldmatrix.sync.aligned.m8n8.x4.shared.b16 {%0,%1,%2,%3}, [%4];"
                 : "=r"(r[0]), "=r"(r[1]), "=r"(r[2]), "=r"(r[3]) : "r"(addr));
}
__device__ __forceinline__ void mma16816(float* c, const uint32_t* a, const uint32_t* b) {
    asm volatile(
        "mma.sync.aligned.m16n8k16.row.col.f32.f16.f16.f32 "
        "{%0,%1,%2,%3}, {%4,%5,%6,%7}, {%8,%9}, {%0,%1,%2,%3};"
        : "+f"(c[0]), "+f"(c[1]), "+f"(c[2]), "+f"(c[3])
        : "r"(a[0]), "r"(a[1]), "r"(a[2]), "r"(a[3]), "r"(b[0]), "r"(b[1]));
}

// ---------------------------------------------------------------------------
__device__ __half g_qh[B_ * T_ * E_], g_kh[B_ * T_ * E_], g_vh[B_ * T_ * E_];
__device__ __half g_wqh[E_ * E_], g_wkh[E_ * E_], g_wvh[E_ * E_];
__device__ __half g_QP[B_ * T_ * E_], g_KP[B_ * T_ * E_];
__device__ __half g_VPt[B_ * E_ * T_];           // transposed [b][e][t]
__device__ __half g_P[B_ * T_ * T_];
__device__ float g_S[B_ * T_ * T_];

struct alignas(16) half8 { __half v[8]; };

// ---------------------------------------------------------------------------
__global__ void __launch_bounds__(256) convert3_kernel(
    const float* __restrict__ x0, const float* __restrict__ x1, const float* __restrict__ x2,
    __half* __restrict__ y0, __half* __restrict__ y1, __half* __restrict__ y2, int n8)
{
    const int z = blockIdx.z;
    const float* x = (z == 0) ? x0 : (z == 1) ? x1 : x2;
    __half* y = (z == 0) ? y0 : (z == 1) ? y1 : y2;
    int i = blockIdx.x * 256 + threadIdx.x;
    if (i >= n8) return;
    float4 f0 = ((const float4*)x)[i * 2];
    float4 f1 = ((const float4*)x)[i * 2 + 1];
    half8 h;
    h.v[0] = __float2half(f0.x); h.v[1] = __float2half(f0.y);
    h.v[2] = __float2half(f0.z); h.v[3] = __float2half(f0.w);
    h.v[4] = __float2half(f1.x); h.v[5] = __float2half(f1.y);
    h.v[6] = __float2half(f1.z); h.v[7] = __float2half(f1.w);
    ((half8*)y)[i] = h;
}

// ---------------------------------------------------------------------------
// Merged projections: grid.z = 0(Q) / 1(K) / 2(V, transposed output).
// NT GEMM 128x128 CTA, 8 warps (4x2), warp tile 32x64, R10 pipeline.
// ---------------------------------------------------------------------------
__global__ void __launch_bounds__(NTH, 2)
proj_fp16(const __half* __restrict__ xq, const __half* __restrict__ xk,
          const __half* __restrict__ xv,
          const __half* __restrict__ wq, const __half* __restrict__ wk,
          const __half* __restrict__ wv,
          const float* __restrict__ bq, const float* __restrict__ bk,
          const float* __restrict__ bv,
          __half* __restrict__ QP, __half* __restrict__ KP, __half* __restrict__ VPt)
{
    const int z = blockIdx.z;
    const __half* pA = (z == 0) ? xq : (z == 1) ? xk : xv;
    const __half* pB = (z == 0) ? wq : (z == 1) ? wk : wv;
    const float* bias = (z == 0) ? bq : (z == 1) ? bk : bv;

    const int bm = blockIdx.y, bn = blockIdx.x;

    extern __shared__ char dsm[];
    const uint32_t sbase = smem_u32(dsm);

    const int t = threadIdx.x;
    const int wid = t >> 5, lane = t & 31;
    const int wm = wid >> 1, wn = wid & 1;
    const int mrow0 = bm * TM, nrow0 = bn * TN;

    const int crow = t >> 1;
    const int cseg = (t & 1) * 2;
    const uint32_t cso = (uint32_t)(crow * ROWB + cseg * 16);

    const uint32_t aoff = (uint32_t)((lane & 15) * ROWB + (lane >> 4) * 16);
    const uint32_t boff = (uint32_t)((((lane & 7) + ((lane >> 1) & 8)) * ROWB) + (lane & 8) * 2);

    float acc[2][8][4] = {};

    const int nchunk = E_ / KC;

    auto prefetch = [&](int ch) {
        const int k0 = ch * KC;
        const uint32_t ss = sbase + (uint32_t)(ch & (NSTAGE - 1)) * STAGEB;
        const size_t ga = (size_t)(mrow0 + crow) * E_ + k0 + cseg * 8;
        const size_t gb = (size_t)(nrow0 + crow) * E_ + k0 + cseg * 8;
        cpasync16(ss + A_OFF + cso,      pA + ga);
        cpasync16(ss + A_OFF + cso + 16, pA + ga + 8);
        cpasync16(ss + B_OFF + cso,      pB + gb);
        cpasync16(ss + B_OFF + cso + 16, pB + gb + 8);
        cp_commit();
    };

    prefetch(0); prefetch(1); prefetch(2);

    for (int ch = 0; ch < nchunk; ch++) {
        if (ch + 2 < nchunk)      cp_wait<2>();
        else if (ch + 1 < nchunk) cp_wait<1>();
        else                      cp_wait<0>();
        __syncthreads();
        if (ch + 3 < nchunk) prefetch(ch + 3);

        const uint32_t ss = sbase + (uint32_t)(ch & (NSTAGE - 1)) * STAGEB;

#pragma unroll
        for (int k16 = 0; k16 < 2; k16++) {
            const uint32_t kb = (uint32_t)(k16 * 32);
            uint32_t ah[2][4], bh[4][4];
#pragma unroll
            for (int mt = 0; mt < 2; mt++)
                ldsm4(ah[mt], ss + A_OFF + (uint32_t)((wm * 32 + mt * 16) * ROWB) + kb + aoff);
#pragma unroll
            for (int n2 = 0; n2 < 4; n2++)
                ldsm4(bh[n2], ss + B_OFF + (uint32_t)((wn * 64 + n2 * 16) * ROWB) + kb + boff);

#pragma unroll
            for (int n2 = 0; n2 < 4; n2++)
#pragma unroll
                for (int mt = 0; mt < 2; mt++)
#pragma unroll
                    for (int h2 = 0; h2 < 2; h2++)
                        mma16816(acc[mt][n2 * 2 + h2], ah[mt], &bh[n2][h2 * 2]);
        }
    }

    __half* Oh = (z == 0) ? QP : (z == 1) ? KP : VPt;

#pragma unroll
    for (int mt = 0; mt < 2; mt++) {
#pragma unroll
        for (int nt = 0; nt < 8; nt++) {
            const float* c = acc[mt][nt];
            const int row = bm * TM + wm * 32 + mt * 16 + (lane >> 2);
            const int col = bn * TN + wn * 64 + nt * 8 + (lane & 3) * 2;
            const float b0 = bias[col], b1 = bias[col + 1];
            if (z < 2) {
#pragma unroll
                for (int h = 0; h < 2; h++) {
                    const int r2 = row + h * 8;
                    __half2 hv = __floats2half2_rn(c[h * 2 + 0] + b0, c[h * 2 + 1] + b1);
                    *(__half2*)(Oh + (size_t)r2 * E_ + col) = hv;
                }
            } else {
#pragma unroll
                for (int h = 0; h < 2; h++) {
                    const int r2 = row + h * 8;
                    const int bb = r2 >> 11, tok = r2 & (T_ - 1);
                    const size_t i0 = ((size_t)bb * E_ + col) * T_ + tok;
                    Oh[i0]      = __float2half(c[h * 2 + 0] + b0);
                    Oh[i0 + T_] = __float2half(c[h * 2 + 1] + b1);
                }
            }
        }
    }
}

// ---------------------------------------------------------------------------
// MODE 2: scores (*1/32 -> fp32 S, causal tile skip)  MODE 3: PV (K truncated)
// bm reversed so heavy tiles schedule first.
// ---------------------------------------------------------------------------
template <int MODE>
__global__ void __launch_bounds__(NTH, 2)
gemm_fp16(const __half* __restrict__ A, const __half* __restrict__ Bm,
          int lda, int ldb, int Kdim,
          float* __restrict__ Of, const int* __restrict__ causalp)
{
    const int bm = (int)gridDim.y - 1 - (int)blockIdx.y;   // heavy-first
    const int bn = blockIdx.x, bz = blockIdx.z;
    const int causal = *causalp;
    if (MODE == 2 && causal && bn > bm) return;

    int Klen = Kdim;
    if (MODE == 3 && causal) Klen = (bm + 1) * TM;

    size_t aOff, bOff;
    if (MODE == 2) { aOff = (size_t)bz * T_ * E_; bOff = (size_t)bz * T_ * E_; }
    else           { aOff = (size_t)bz * T_ * T_; bOff = (size_t)bz * E_ * T_; }
    const __half* pA = A + aOff;
    const __half* pB = Bm + bOff;

    extern __shared__ char dsm[];
    const uint32_t sbase = smem_u32(dsm);

    const int t = threadIdx.x;
    const int wid = t >> 5, lane = t & 31;
    const int wm = wid >> 1, wn = wid & 1;
    const int mrow0 = bm * TM, nrow0 = bn * TN;

    const int crow = t >> 1;
    const int cseg = (t & 1) * 2;
    const uint32_t cso = (uint32_t)(crow * ROWB + cseg * 16);

    const uint32_t aoff = (uint32_t)((lane & 15) * ROWB + (lane >> 4) * 16);
    const uint32_t boff = (uint32_t)((((lane & 7) + ((lane >> 1) & 8)) * ROWB) + (lane & 8) * 2);

    float acc[2][8][4] = {};

    const int nchunk = Klen / KC;

    auto prefetch = [&](int ch) {
        const int k0 = ch * KC;
        const uint32_t ss = sbase + (uint32_t)(ch & (NSTAGE - 1)) * STAGEB;
        const size_t ga = (size_t)(mrow0 + crow) * lda + k0 + cseg * 8;
        const size_t gb = (size_t)(nrow0 + crow) * ldb + k0 + cseg * 8;
        cpasync16(ss + A_OFF + cso,      pA + ga);
        cpasync16(ss + A_OFF + cso + 16, pA + ga + 8);
        cpasync16(ss + B_OFF + cso,      pB + gb);
        cpasync16(ss + B_OFF + cso + 16, pB + gb + 8);
        cp_commit();
    };

    prefetch(0);
    if (nchunk > 1) prefetch(1);
    if (nchunk > 2) prefetch(2);

    for (int ch = 0; ch < nchunk; ch++) {
        if (ch + 2 < nchunk)      cp_wait<2>();
        else if (ch + 1 < nchunk) cp_wait<1>();
        else                      cp_wait<0>();
        __syncthreads();
        if (ch + 3 < nchunk) prefetch(ch + 3);

        const uint32_t ss = sbase + (uint32_t)(ch & (NSTAGE - 1)) * STAGEB;

#pragma unroll
        for (int k16 = 0; k16 < 2; k16++) {
            const uint32_t kb = (uint32_t)(k16 * 32);
            uint32_t ah[2][4], bh[4][4];
#pragma unroll
            for (int mt = 0; mt < 2; mt++)
                ldsm4(ah[mt], ss + A_OFF + (uint32_t)((wm * 32 + mt * 16) * ROWB) + kb + aoff);
#pragma unroll
            for (int n2 = 0; n2 < 4; n2++)
                ldsm4(bh[n2], ss + B_OFF + (uint32_t)((wn * 64 + n2 * 16) * ROWB) + kb + boff);

#pragma unroll
            for (int n2 = 0; n2 < 4; n2++)
#pragma unroll
                for (int mt = 0; mt < 2; mt++)
#pragma unroll
                    for (int h2 = 0; h2 < 2; h2++)
                        mma16816(acc[mt][n2 * 2 + h2], ah[mt], &bh[n2][h2 * 2]);
        }
    }

#pragma unroll
    for (int mt = 0; mt < 2; mt++) {
#pragma unroll
        for (int nt = 0; nt < 8; nt++) {
            const float* c = acc[mt][nt];
            const int row = bm * TM + wm * 32 + mt * 16 + (lane >> 2);
            const int col = bn * TN + wn * 64 + nt * 8 + (lane & 3) * 2;
            if constexpr (MODE == 2) {
                const float sc = 0.03125f;
#pragma unroll
                for (int h = 0; h < 2; h++) {
                    const int r2 = row + h * 8;
                    float2 f = make_float2(c[h * 2 + 0] * sc, c[h * 2 + 1] * sc);
                    *(float2*)(Of + (size_t)bz * T_ * T_ + (size_t)r2 * T_ + col) = f;
                }
            } else {
#pragma unroll
                for (int h = 0; h < 2; h++) {
                    const int r2 = row + h * 8;
                    float2 f = make_float2(c[h * 2 + 0], c[h * 2 + 1]);
                    *(float2*)(Of + (size_t)bz * T_ * E_ + (size_t)r2 * E_ + col) = f;
                }
            }
        }
    }
}

// ---------------------------------------------------------------------------
// Row softmax, single global read: row cached in 8 regs/thread.
// ---------------------------------------------------------------------------
__global__ void __launch_bounds__(256) softmax_kernel(const float* __restrict__ S,
                                                      __half* __restrict__ P,
                                                      const int* __restrict__ causalp)
{
    const int b = blockIdx.y, i = blockIdx.x;
    const float* row = S + ((size_t)b * T_ + i) * T_;
    __half* ph = P + ((size_t)b * T_ + i) * T_;
    const int causal = *causalp;
    const int jmax = causal ? i : (T_ - 1);
    const int t = threadIdx.x;

    __shared__ float red[256];

    float vals[8];
    float lm = -3.4e38f;
#pragma unroll
    for (int it = 0; it < 8; it++) {
        const int j = t + it * 256;
        vals[it] = (j <= jmax) ? row[j] : -3.4e38f;
        lm = fmaxf(lm, vals[it]);
    }
    red[t] = lm; __syncthreads();
    for (int s = 128; s > 0; s >>= 1) {
        if (t < s) red[t] = fmaxf(red[t], red[t + s]);
        __syncthreads();
    }
    const float m = red[0];
    __syncthreads();

    float ls = 0.f;
#pragma unroll
    for (int it = 0; it < 8; it++) {
        const int j = t + it * 256;
        if (j <= jmax) {
            const float e = __expf(vals[it] - m);
            vals[it] = e;
            ls += e;
        }
    }
    red[t] = ls; __syncthreads();
    for (int s = 128; s > 0; s >>= 1) {
        if (t < s) red[t] += red[t + s];
        __syncthreads();
    }
    const float inv = 1.f / red[0];

#pragma unroll
    for (int it = 0; it < 8; it++) {
        const int j = t + it * 256;
        if (j <= jmax) ph[j] = __float2half(vals[it] * inv);
    }
    if (causal) {
        const int zend = ((i >> 7) + 1) << 7;
        for (int j = i + 1 + t; j < zend; j += 256) ph[j] = __float2half(0.f);
    }
}

// ---------------------------------------------------------------------------
extern "C" void kernel_launch(void* const* d_in, const int* in_sizes, int n_in,
                              void* d_out, int out_size)
{
    const float* q    = (const float*)d_in[0];
    const float* k    = (const float*)d_in[1];
    const float* v    = (const float*)d_in[2];
    const float* wq_w = (const float*)d_in[3];
    const float* wq_b = (const float*)d_in[4];
    const float* wk_w = (const float*)d_in[5];
    const float* wk_b = (const float*)d_in[6];
    const float* wv_w = (const float*)d_in[7];
    const float* wv_b = (const float*)d_in[8];
    const int* causal = (const int*)d_in[9];
    float* out = (float*)d_out;

    void *qh, *kh, *vh, *wqh, *wkh, *wvh, *QP, *KP, *VPt, *P, *Sp;
    cudaGetSymbolAddress(&qh, g_qh);   cudaGetSymbolAddress(&kh, g_kh);
    cudaGetSymbolAddress(&vh, g_vh);
    cudaGetSymbolAddress(&wqh, g_wqh); cudaGetSymbolAddress(&wkh, g_wkh);
    cudaGetSymbolAddress(&wvh, g_wvh);
    cudaGetSymbolAddress(&QP, g_QP);   cudaGetSymbolAddress(&KP, g_KP);
    cudaGetSymbolAddress(&VPt, g_VPt); cudaGetSymbolAddress(&P, g_P);
    cudaGetSymbolAddress(&Sp, g_S);

    cudaFuncSetAttribute(proj_fp16,    cudaFuncAttributeMaxDynamicSharedMemorySize, DSMEM);
    cudaFuncSetAttribute(gemm_fp16<2>, cudaFuncAttributeMaxDynamicSharedMemorySize, DSMEM);
    cudaFuncSetAttribute(gemm_fp16<3>, cudaFuncAttributeMaxDynamicSharedMemorySize, DSMEM);

    // 1) fp32 -> fp16 converts
    const int nQKV8 = B_ * T_ * E_ / 8, nW8 = E_ * E_ / 8;
    dim3 gz1(nQKV8 / 256, 1, 3), gz2(nW8 / 256, 1, 3);
    convert3_kernel<<<gz1, 256>>>(q, k, v, (__half*)qh, (__half*)kh, (__half*)vh, nQKV8);
    convert3_kernel<<<gz2, 256>>>(wq_w, wk_w, wv_w,
                                  (__half*)wqh, (__half*)wkh, (__half*)wvh, nW8);

    // 2) All three projections in ONE launch (grid.z = Q/K/V)
    dim3 gp(E_ / TN, (B_ * T_) / TM, 3);   // 8 x 64 x 3 = 1536 CTAs
    proj_fp16<<<gp, NTH, DSMEM>>>((__half*)qh, (__half*)kh, (__half*)vh,
                                  (__half*)wqh, (__half*)wkh, (__half*)wvh,
                                  wq_b, wk_b, wv_b,
                                  (__half*)QP, (__half*)KP, (__half*)VPt);

    // 3) Scores (heavy-first, causal skip)
    dim3 gs(T_ / TN, T_ / TM, B_);         // 16 x 16 x 4
    gemm_fp16<2><<<gs, NTH, DSMEM>>>((__half*)QP, (__half*)KP, E_, E_, E_,
                                     (float*)Sp, causal);

    // 4) Softmax -> fp16 P
    dim3 gm(T_, B_);
    softmax_kernel<<<gm, 256>>>((const float*)Sp, (__half*)P, causal);

    // 5) PV (heavy-first, K truncation)
    dim3 gv(E_ / TN, T_ / TM, B_);         // 8 x 16 x 4
    gemm_fp16<3><<<gv, NTH, DSMEM>>>((__half*)P, (__half*)VPt, T_, T_, T_,
                                     out, causal);
}